// round 15
// baseline (speedup 1.0000x reference)
#include <cuda_runtime.h>

#define NN 4096
#define NF 512
#define NH 60
#define NC 4
#define MAXDEG 128
#define PAD 64   // padded feature stride

#define GEMM_BLOCKS 256   // 64 row-blocks x 4 K-chunks
#define SCAN_BLOCKS 2048
#define LAYER_BLOCKS 512  // one wave guaranteed (smem cap 7/SM -> 1036 resident)

// ---- static device scratch (no allocations allowed) ----
__device__ float  g_d[NN];              // column sums of A_tilde (init 1.0 for self loop)
__device__ int    g_cnt[NN];            // per-row nnz count
__device__ int    g_degp[NN];           // padded degree (multiple of 8)
__device__ int    g_col[NN * MAXDEG];   // raw CSR columns (from scan)
__device__ float  g_wv[NN * MAXDEG];    // raw CSR values (sigmoid(P)*adj)
__device__ float2 g_edge[NN * MAXDEG];  // prescaled edges: {bitcast(j), w*dis_i*dis_j}
__device__ float  g_self[NN];           // 1/d_i  (self-loop weight dis_i^2)
__device__ float  g_bufA[NN * PAD];
__device__ float  g_bufB[NN * PAD];
__device__ int    g_bar;                // grid barrier counter (reset by k_init)

// ---------------- kernel 1: init ----------------
__global__ void k_init() {
    int t = blockIdx.x * blockDim.x + threadIdx.x;
    if (t < NN) { g_d[t] = 1.0f; g_cnt[t] = 0; }
    if (t == 0) g_bar = 0;
}

// ---------------- kernel 2 (FAT): scan sub_adj  ||  Z0 = X @ W1 ----------------
__global__ void __launch_bounds__(256) k_fat(const float* __restrict__ X,
                                             const float* __restrict__ W1,
                                             const float4* __restrict__ adj,
                                             const float* __restrict__ P) {
    __shared__ float Xs_t[32 * 68];   // [kk][row], stride 68
    __shared__ float Ws[32 * NH];     // [kk][col]

    int tid = threadIdx.x;

    if (blockIdx.x < GEMM_BLOCKS) {
        // ===================== GEMM role =====================
        int rb = blockIdx.x >> 2;
        int ky = blockIdx.x & 3;
        int rowbase = rb * 64;
        int kbase = ky * 128;

        bool active = (tid < 240);
        int cg = tid % 15, rt = tid / 15;
        int c0 = cg * 4;
        int r0 = active ? rt * 4 : 0;

        float acc[4][4];
        #pragma unroll
        for (int i = 0; i < 4; i++)
            #pragma unroll
            for (int j = 0; j < 4; j++) acc[i][j] = 0.f;

        for (int s = 0; s < 4; s++) {
            int kb = kbase + s * 32;
            #pragma unroll
            for (int it = 0; it < 2; it++) {
                int idx = tid + it * 256;
                int r = idx & 63, k4 = idx >> 6;
                float4 g = *(const float4*)&X[(rowbase + r) * NF + kb + k4 * 4];
                Xs_t[(k4 * 4 + 0) * 68 + r] = g.x;
                Xs_t[(k4 * 4 + 1) * 68 + r] = g.y;
                Xs_t[(k4 * 4 + 2) * 68 + r] = g.z;
                Xs_t[(k4 * 4 + 3) * 68 + r] = g.w;
            }
            for (int idx = tid; idx < 480; idx += 256)
                ((float4*)Ws)[idx] = ((const float4*)&W1[kb * NH])[idx];
            __syncthreads();

            #pragma unroll 8
            for (int kk = 0; kk < 32; kk++) {
                float4 x4 = *(const float4*)&Xs_t[kk * 68 + r0];
                float4 w4 = *(const float4*)&Ws[kk * NH + c0];
                float xv[4] = {x4.x, x4.y, x4.z, x4.w};
                float wv[4] = {w4.x, w4.y, w4.z, w4.w};
                #pragma unroll
                for (int i = 0; i < 4; i++)
                    #pragma unroll
                    for (int j = 0; j < 4; j++)
                        acc[i][j] += xv[i] * wv[j];
            }
            __syncthreads();
        }
        if (active) {
            #pragma unroll
            for (int i = 0; i < 4; i++) {
                float* o = &g_bufA[(rowbase + r0 + i) * PAD + c0];
                atomicAdd(o + 0, acc[i][0]);
                atomicAdd(o + 1, acc[i][1]);
                atomicAdd(o + 2, acc[i][2]);
                atomicAdd(o + 3, acc[i][3]);
            }
        }
    } else {
        // ===================== scan role =====================
        const int T = SCAN_BLOCKS * 256;
        int t = (blockIdx.x - GEMM_BLOCKS) * 256 + tid;
        float4 a[8];
        #pragma unroll
        for (int u = 0; u < 8; u++) a[u] = adj[t + u * T];

        #pragma unroll
        for (int u = 0; u < 8; u++) {
            float4 a4 = a[u];
            if (a4.x == 0.f && a4.y == 0.f && a4.z == 0.f && a4.w == 0.f) continue;
            int base = (t + u * T) << 2;
            int i = base >> 12;
            int j0 = base & (NN - 1);
            float av[4] = {a4.x, a4.y, a4.z, a4.w};
            #pragma unroll
            for (int q = 0; q < 4; q++) {
                float aa = av[q];
                if (aa == 0.f) continue;
                int j = j0 + q;
                int tri = (i >= j) ? (i * (i + 1) / 2 + j) : (j * (j + 1) / 2 + i);
                float p = P[tri];
                float w = aa / (1.f + __expf(-p));
                atomicAdd(&g_d[j], w);
                int s = atomicAdd(&g_cnt[i], 1);
                if (s < MAXDEG) {
                    g_col[i * MAXDEG + s] = j;
                    g_wv[i * MAXDEG + s] = w;
                }
            }
        }
    }
}

// ---------------- software grid barrier (single wave guaranteed) ----------------
__device__ __forceinline__ void grid_bar(int target) {
    __syncthreads();
    if (threadIdx.x == 0) {
        __threadfence();                 // release prior writes
        atomicAdd(&g_bar, 1);
        while (*(volatile int*)&g_bar < target) __nanosleep(64);
        __threadfence();                 // acquire peers' writes
    }
    __syncthreads();
}

// ---------------- SpMM phase (device fn) ----------------
// 1 row per warp. Batch-8 edge gathers. Zin/out PAD(64)-strided; lane owns
// feature cols {2*lane,2*lane+1} as float2. Wsh in smem, stride NH (MODE 0)
// or NC (MODE 1); pad-lane accesses provably harmless.
template <int MODE>
__device__ __forceinline__ void spmm_phase(const float* __restrict__ Zin,
                                           const float* __restrict__ bias,
                                           const float* __restrict__ Wsh,
                                           const float* __restrict__ lin_b,
                                           float* __restrict__ out,
                                           float* hrow,   // this warp's hsh row (PAD floats)
                                           int w, int lane, int row) {
    const float2* Z2 = (const float2*)Zin;
    int deg = g_degp[row];
    const float2* ep = g_edge + row * MAXDEG;

    float2 acc = make_float2(0.f, 0.f);
    for (int e = 0; e < deg; e += 8) {
        float2 q[8];
        #pragma unroll
        for (int u = 0; u < 8; u++) q[u] = ep[e + u];
        float2 z[8];
        #pragma unroll
        for (int u = 0; u < 8; u++) z[u] = Z2[__float_as_int(q[u].x) * 32 + lane];
        #pragma unroll
        for (int u = 0; u < 8; u++) {
            acc.x += q[u].y * z[u].x;
            acc.y += q[u].y * z[u].y;
        }
    }

    float2 h = make_float2(0.f, 0.f);
    if (lane < NH / 2) {
        float2 bi = ((const float2*)bias)[lane];
        float sw = g_self[row];
        float2 zr = Z2[row * 32 + lane];
        h.x = acc.x + sw * zr.x + bi.x;
        h.y = acc.y + sw * zr.y + bi.y;
        if (MODE == 0) { h.x = fmaxf(h.x, 0.f); h.y = fmaxf(h.y, 0.f); }
    }
    *(float2*)&hrow[2 * lane] = h;
    __syncwarp();

    if (MODE == 0) {
        float2 z = make_float2(0.f, 0.f);
        #pragma unroll
        for (int k = 0; k < NH; k++) {
            float2 wv = *(const float2*)&Wsh[k * NH + 2 * lane];  // conflict-free
            float hk = hrow[k];                                    // broadcast
            z.x += hk * wv.x;
            z.y += hk * wv.y;
        }
        ((float2*)out)[row * 32 + lane] = z;
    } else {
        float logit = 0.f;
        if (lane < NC) {
            logit = lin_b[lane];
            #pragma unroll
            for (int k = 0; k < NH; k++) logit += hrow[k] * Wsh[k * NC + lane];
        }
        float l0 = __shfl_sync(0xffffffffu, logit, 0);
        float l1 = __shfl_sync(0xffffffffu, logit, 1);
        float l2 = __shfl_sync(0xffffffffu, logit, 2);
        float l3 = __shfl_sync(0xffffffffu, logit, 3);
        if (lane < NC) {
            float m = fmaxf(fmaxf(l0, l1), fmaxf(l2, l3));
            float s = __expf(l0 - m) + __expf(l1 - m) + __expf(l2 - m) + __expf(l3 - m);
            out[row * NC + lane] = logit - m - logf(s);
        }
    }
}

// ---------------- kernel 3 (merged): prep + 3 GCN layers + head ----------------
// grid = LAYER_BLOCKS(512) x 256 thr, 8 rows/block. One wave; software grid
// barriers between phases. All weights staged to smem ONCE at start.
__global__ void __launch_bounds__(256) k_layers(const float* __restrict__ b1,
                                                const float* __restrict__ W2,
                                                const float* __restrict__ b2,
                                                const float* __restrict__ W3,
                                                const float* __restrict__ b3,
                                                const float* __restrict__ lin_w,
                                                const float* __restrict__ lin_b,
                                                float* __restrict__ bufA,
                                                float* __restrict__ bufB,
                                                float* __restrict__ out) {
    __shared__ float W2s[NH * NH];   // 3600
    __shared__ float W3s[NH * NH];   // 3600
    __shared__ float LWs[NH * NC];   // 240
    __shared__ float hsh[8][PAD];

    int tid = threadIdx.x;
    int w = tid >> 5, lane = tid & 31;
    int row = blockIdx.x * 8 + w;

    // stage all weights once (float4)
    for (int idx = tid; idx < NH * NH / 4; idx += 256) {
        ((float4*)W2s)[idx] = ((const float4*)W2)[idx];
        ((float4*)W3s)[idx] = ((const float4*)W3)[idx];
    }
    if (tid < NH * NC / 4) ((float4*)LWs)[tid] = ((const float4*)lin_w)[tid];

    // ---- phase 0: prescale edges + pad degree to multiple of 8 ----
    {
        float ri = rsqrtf(g_d[row]);
        int deg = min(g_cnt[row], MAXDEG);
        int padded = (deg + 7) & ~7;
        if (lane == 0) { g_self[row] = ri * ri; g_degp[row] = padded; }
        int base = row * MAXDEG;
        for (int e = lane; e < padded; e += 32) {
            if (e < deg) {
                int j = g_col[base + e];
                float ww = g_wv[base + e] * ri * rsqrtf(g_d[j]);
                g_edge[base + e] = make_float2(__int_as_float(j), ww);
            } else {
                g_edge[base + e] = make_float2(__int_as_float(0), 0.f);
            }
        }
    }
    grid_bar(LAYER_BLOCKS);

    // ---- phase 1: bufB = relu(spmm(bufA)+b1) @ W2 ----
    spmm_phase<0>(bufA, b1, W2s, nullptr, bufB, hsh[w], w, lane, row);
    grid_bar(2 * LAYER_BLOCKS);

    // ---- phase 2: bufA = relu(spmm(bufB)+b2) @ W3 ----
    spmm_phase<0>(bufB, b2, W3s, nullptr, bufA, hsh[w], w, lane, row);
    grid_bar(3 * LAYER_BLOCKS);

    // ---- phase 3: out = log_softmax((spmm(bufA)+b3) @ lin_w + lin_b) ----
    spmm_phase<1>(bufA, b3, LWs, lin_b, out, hsh[w], w, lane, row);
}

// ---------------- launch ----------------
extern "C" void kernel_launch(void* const* d_in, const int* in_sizes, int n_in,
                              void* d_out, int out_size) {
    const float* x     = (const float*)d_in[0];
    const float* adj   = (const float*)d_in[1];
    const float* P     = (const float*)d_in[2];
    const float* W1    = (const float*)d_in[3];
    const float* b1    = (const float*)d_in[4];
    const float* W2    = (const float*)d_in[5];
    const float* b2    = (const float*)d_in[6];
    const float* W3    = (const float*)d_in[7];
    const float* b3    = (const float*)d_in[8];
    const float* lin_w = (const float*)d_in[9];
    const float* lin_b = (const float*)d_in[10];
    float* out = (float*)d_out;

    float *bufA, *bufB;
    cudaGetSymbolAddress((void**)&bufA, g_bufA);
    cudaGetSymbolAddress((void**)&bufB, g_bufB);

    cudaMemsetAsync(bufA, 0, NN * PAD * sizeof(float));         // gemm accumulator
    k_init<<<16, 256>>>();                                      // g_d=1, g_cnt=0, g_bar=0
    k_fat<<<GEMM_BLOCKS + SCAN_BLOCKS, 256>>>(x, W1, (const float4*)adj, P);
    k_layers<<<LAYER_BLOCKS, 256>>>(b1, W2, b2, W3, b3, lin_w, lin_b,
                                    bufA, bufB, out);
}